// round 15
// baseline (speedup 1.0000x reference)
#include <cuda_runtime.h>
#include <math.h>

#define HH 160
#define WW 192
#define DD 160
#define NSZ (HH*WW*DD)          // 4,915,200
#define N3  (3*NSZ)             // 14,745,600
#define NROWS (HH*WW)           // 30720
#define CHUNK 16
#define LPB 4                   // lines per block in k_boxd_fwd
#define TPL (DD/4)              // threads per line (40)
#define NQ  (NSZ/4)             // 1,228,800 float4 cells
#define NBCHAIN (NQ/256)        // 4800 chain blocks

// ---- scratch (device globals; no allocations allowed) ----
static __device__ float  d_flowA[N3];
static __device__ float  d_flowB[N3];
static __device__ float  d_m[N3];
static __device__ float  d_v[N3];
static __device__ float  d_vh[N3];
static __device__ float  d_A[N3];     // ping buffer, 3 fields of NSZ
static __device__ float  d_Bf[N3];    // pong buffer, 3 fields of NSZ
static __device__ float  d_J[2*NSZ];  // S_J, S_JJ (precomputed from y)
static __device__ float  d_val[NSZ];  // warped image Iw (per iter)
static __device__ float  d_gx[N3];    // trilerp jacobian (per iter)
static __device__ double d_part[NBCHAIN];

#define WSF  729.0f
#define INVN (1.0f/4915200.0f)
// reg-gradient coefficients: 2 / (3 * 3*(L-1)*other*other)
#define CH_ (2.0f/43960320.0f)  // 9*159*192*160
#define CW_ (2.0f/44006400.0f)  // 9*160*191*160
#define CD_ (2.0f/43960320.0f)  // 9*160*192*159

__device__ __forceinline__ float4 f4z() { return make_float4(0.f, 0.f, 0.f, 0.f); }
__device__ __forceinline__ float4 operator+(float4 a, float4 b) {
    return make_float4(a.x + b.x, a.y + b.y, a.z + b.z, a.w + b.w);
}
__device__ __forceinline__ float4 operator-(float4 a, float4 b) {
    return make_float4(a.x - b.x, a.y - b.y, a.z - b.z, a.w - b.w);
}

__device__ __forceinline__ float* bufsel(int s)
{
    return (s == 0) ? d_A : ((s == 1) ? d_Bf : d_J);
}

// flow source: 0 = external (init), 1 = flowA, 2 = flowB
__device__ __forceinline__ const float* flowsel(int s, const float* ext)
{
    return (s == 0) ? ext : ((s == 1) ? d_flowA : d_flowB);
}

// ---------------------------------------------------------------------------
// 9-tap window sums of a 12-float strip (q0|q1|q2) -> 4 outputs
// out[o] = sum of strip[o .. o+8]
// ---------------------------------------------------------------------------
__device__ __forceinline__ float4 win9(float4 tm, float4 tc, float4 tp)
{
    float b0 = tm.x + tm.y + tm.z + tm.w + tc.x + tc.y + tc.z + tc.w + tp.x;
    float b1 = b0 - tm.x + tp.y;
    float b2 = b1 - tm.y + tp.z;
    float b3 = b2 - tm.z + tp.w;
    return make_float4(b0, b1, b2, b3);
}

// ---------------------------------------------------------------------------
// trilinear corner fetch + lerp + gradient wrt coords (zero outside)
// ---------------------------------------------------------------------------
__device__ __forceinline__ void trilerp_all(const float* __restrict__ xv,
    float c0, float c1, float c2,
    float& val, float& gx0, float& gx1, float& gx2)
{
    float l0 = floorf(c0), l1 = floorf(c1), l2 = floorf(c2);
    int i0 = (int)l0, j0 = (int)l1, k0 = (int)l2;
    float f0 = c0 - l0, f1 = c1 - l1, f2 = c2 - l2;
    float v[2][2][2];
#pragma unroll
    for (int a = 0; a < 2; a++) {
        int ii = i0 + a; bool oa = (ii >= 0 && ii < HH);
#pragma unroll
        for (int b = 0; b < 2; b++) {
            int jj = j0 + b; bool ob = oa && (jj >= 0 && jj < WW);
            int base = (ii * WW + jj) * DD;
#pragma unroll
            for (int c = 0; c < 2; c++) {
                int kk = k0 + c; bool oc = ob && (kk >= 0 && kk < DD);
                v[a][b][c] = oc ? __ldg(&xv[base + kk]) : 0.f;
            }
        }
    }
    float u00 = v[0][0][0] * (1.f - f2) + v[0][0][1] * f2;
    float u01 = v[0][1][0] * (1.f - f2) + v[0][1][1] * f2;
    float u10 = v[1][0][0] * (1.f - f2) + v[1][0][1] * f2;
    float u11 = v[1][1][0] * (1.f - f2) + v[1][1][1] * f2;
    float ta = u00 * (1.f - f1) + u01 * f1;
    float tb = u10 * (1.f - f1) + u11 * f1;
    val = ta * (1.f - f0) + tb * f0;
    gx0 = tb - ta;
    gx1 = (1.f - f0) * (u01 - u00) + f0 * (u11 - u10);
    float d00 = v[0][0][1] - v[0][0][0], d01 = v[0][1][1] - v[0][1][0];
    float d10 = v[1][0][1] - v[1][0][0], d11 = v[1][1][1] - v[1][1][0];
    gx2 = (1.f - f0) * ((1.f - f1) * d00 + f1 * d01)
        + f0 * ((1.f - f1) * d10 + f1 * d11);
}

// ---------------------------------------------------------------------------
// warp + products + D-axis box (vectorized win9 form) -> d_A[0..2];
// also stores Iw -> d_val and the trilerp jacobian -> d_gx (float4 stores).
// 4 lines per block; each thread owns 4 consecutive k of one line.
// ---------------------------------------------------------------------------
__global__ void k_boxd_fwd(const float* __restrict__ x, const float* __restrict__ y,
                           const float* __restrict__ init, int sel)
{
    const float* fl = flowsel(sel, init);
    int tid = threadIdx.x;              // 0..159
    int sub = tid / TPL;                // line within block
    int l   = tid % TPL;                // chunk along D
    int line = blockIdx.x * LPB + sub;
    int i = line / WW, j = line % WW;
    int k0 = l * 4;
    int p = line * DD + k0;

    __shared__ float s[3][LPB][DD + 8];

    // zero pad zones (4 floats each side per field per line)
    if (l < 4) {
#pragma unroll
        for (int f = 0; f < 3; f++) {
            s[f][sub][l] = 0.f;
            s[f][sub][DD + 4 + l] = 0.f;
        }
    }

    float4 f0v = *(const float4*)(fl + p);
    float4 f1v = *(const float4*)(fl + NSZ + p);
    float4 f2v = *(const float4*)(fl + 2 * NSZ + p);
    float4 yv  = *(const float4*)(y + p);

    float Iw[4], g0[4], g1[4], g2[4];
#pragma unroll
    for (int o = 0; o < 4; o++) {
        float c0 = (float)i + ((const float*)&f0v)[o];
        float c1 = (float)j + ((const float*)&f1v)[o];
        float c2 = (float)(k0 + o) + ((const float*)&f2v)[o];
        trilerp_all(x, c0, c1, c2, Iw[o], g0[o], g1[o], g2[o]);
    }

    *(float4*)(d_val + p)          = make_float4(Iw[0], Iw[1], Iw[2], Iw[3]);
    *(float4*)(d_gx + p)           = make_float4(g0[0], g0[1], g0[2], g0[3]);
    *(float4*)(d_gx + NSZ + p)     = make_float4(g1[0], g1[1], g1[2], g1[3]);
    *(float4*)(d_gx + 2 * NSZ + p) = make_float4(g2[0], g2[1], g2[2], g2[3]);

    const float* yy = (const float*)&yv;
    *(float4*)&s[0][sub][4 + k0] = make_float4(Iw[0], Iw[1], Iw[2], Iw[3]);
    *(float4*)&s[1][sub][4 + k0] = make_float4(Iw[0] * Iw[0], Iw[1] * Iw[1],
                                               Iw[2] * Iw[2], Iw[3] * Iw[3]);
    *(float4*)&s[2][sub][4 + k0] = make_float4(Iw[0] * yy[0], Iw[1] * yy[1],
                                               Iw[2] * yy[2], Iw[3] * yy[3]);
    __syncthreads();

    // D-box: out[k] = sum s_arr[k .. k+8] (pad offset 4 built in)
#pragma unroll
    for (int f = 0; f < 3; f++) {
        float4 q0 = *(const float4*)&s[f][sub][k0];
        float4 q1 = *(const float4*)&s[f][sub][k0 + 4];
        float4 q2 = *(const float4*)&s[f][sub][k0 + 8];
        *(float4*)(d_A + f * NSZ + p) = win9(q0, q1, q2);
    }
}

// D-axis box of (y, y*y) -> d_A[0..1]
__global__ void k_boxd_pre(const float* __restrict__ y)
{
    int line = blockIdx.x;
    int k = threadIdx.x;
    int p = line * DD + k;
    float yy = y[p];
    __shared__ float s[2][DD + 8];
    s[0][4 + k] = yy; s[1][4 + k] = yy * yy;
    if (k < 4) {
        s[0][k] = 0.f; s[1][k] = 0.f;
        s[0][DD + 4 + k] = 0.f; s[1][DD + 4 + k] = 0.f;
    }
    __syncthreads();
    float r0 = 0.f, r1 = 0.f;
#pragma unroll
    for (int t = 0; t < 9; t++) { r0 += s[0][k + t]; r1 += s[1][k + t]; }
    d_A[p] = r0; d_A[NSZ + p] = r1;
}

// ---------------------------------------------------------------------------
// Strided-axis box, one field per thread (field = blockIdx.y), sliding
// window with software pipelining (3 batches of 5 steps, 10 loads in flight).
// ---------------------------------------------------------------------------
__global__ void k_box1(int ssel, int dsel, int L, int S, int nlo4, int nchunk,
                       int total)
{
    int tid = blockIdx.x * 256 + threadIdx.x;
    if (tid >= total) return;
    int f = blockIdx.y;
    int lo4 = tid % nlo4;
    int rest = tid / nlo4;
    int chunk = rest % nchunk;
    int hi = rest / nchunk;

    const float* __restrict__ in = bufsel(ssel) + f * NSZ;
    float* __restrict__ out = bufsel(dsel) + f * NSZ;

    int c0 = chunk * CHUNK;
    int base = hi * L * S + lo4 * 4;

    // initial 9-tap window: all loads independent
    float4 w[9];
#pragma unroll
    for (int t = 0; t < 9; t++) {
        int a = c0 - 4 + t;
        w[t] = ((unsigned)a < (unsigned)L) ? *(const float4*)(in + base + a * S) : f4z();
    }
    float4 s = ((((((((w[0] + w[1]) + w[2]) + w[3]) + w[4]) + w[5]) + w[6]) + w[7]) + w[8]);
    *(float4*)(out + base + c0 * S) = s;

    // 15 sliding steps in 3 batches of 5 (10 loads in flight per batch)
#pragma unroll
    for (int bb = 0; bb < 3; bb++) {
        float4 vin[5], vout[5];
#pragma unroll
        for (int u = 0; u < 5; u++) {
            int o = bb * 5 + u + 1;
            int ain = c0 + o + 4, aout = c0 + o - 5;
            vin[u]  = ((unsigned)ain < (unsigned)L) ? *(const float4*)(in + base + ain * S)  : f4z();
            vout[u] = (aout >= 0)                   ? *(const float4*)(in + base + aout * S) : f4z();
        }
#pragma unroll
        for (int u = 0; u < 5; u++) {
            int o = bb * 5 + u + 1;
            s = s + vin[u] - vout[u];
            *(float4*)(out + base + (c0 + o) * S) = s;
        }
    }
}

// ---------------------------------------------------------------------------
// per-lane NCC partials from full window sums
// ---------------------------------------------------------------------------
__device__ __forceinline__ void gcalc(float SI, float SII, float SIJ,
                                      float SJ, float SJJ,
                                      float& gI, float& gII, float& gIJ)
{
    float uI = SI / WSF, uJ = SJ / WSF;
    float cross = SIJ - uJ * SI - uI * SJ + uI * uJ * WSF;
    float Iv = SII - 2.f * uI * SI + uI * uI * WSF;
    float Jv = SJJ - 2.f * uJ * SJ + uJ * uJ * WSF;
    float Dn = Iv * Jv + 1e-5f;
    float t0 = cross / Dn;
    float q  = 2.f * t0;
    float r  = t0 * t0 * Jv;
    gI  = -q * uJ + 2.f * r * uI;
    gII = -r;
    gIJ = q;
}

// ---------------------------------------------------------------------------
// Forward H-axis box fused with gf: completes window sums in registers and
// emits g-fields.  in: d_Bf (D,W-boxed), d_J  ->  out: d_A = (gI,gII,gIJ)
// ---------------------------------------------------------------------------
__global__ void k_boxh_gf(void)
{
    const int nlo4 = (WW * DD) / 4;   // 7680
    const int nch  = HH / 8;          // 20
    int tid = blockIdx.x * 256 + threadIdx.x;
    if (tid >= nlo4 * nch) return;
    int lo4 = tid % nlo4;
    int chunk = tid / nlo4;
    int c0 = chunk * 8;
    int base = lo4 * 4;
    const int S = WW * DD;

    float4 s0 = f4z(), s1 = f4z(), s2 = f4z();
#pragma unroll
    for (int t = -4; t <= 4; t++) {
        int a = c0 + t;
        if ((unsigned)a < (unsigned)HH) {
            s0 = s0 + *(const float4*)(d_Bf + base + a * S);
            s1 = s1 + *(const float4*)(d_Bf + NSZ + base + a * S);
            s2 = s2 + *(const float4*)(d_Bf + 2 * NSZ + base + a * S);
        }
    }

#pragma unroll
    for (int o = 0; o < 8; o++) {
        int a = c0 + o;
        if (o > 0) {
            int ain = a + 4, aout = a - 5;
            if ((unsigned)ain < (unsigned)HH) {
                s0 = s0 + *(const float4*)(d_Bf + base + ain * S);
                s1 = s1 + *(const float4*)(d_Bf + NSZ + base + ain * S);
                s2 = s2 + *(const float4*)(d_Bf + 2 * NSZ + base + ain * S);
            }
            if (aout >= 0) {
                s0 = s0 - *(const float4*)(d_Bf + base + aout * S);
                s1 = s1 - *(const float4*)(d_Bf + NSZ + base + aout * S);
                s2 = s2 - *(const float4*)(d_Bf + 2 * NSZ + base + aout * S);
            }
        }
        float4 J0 = *(const float4*)(d_J + base + a * S);
        float4 J1 = *(const float4*)(d_J + NSZ + base + a * S);
        float4 o0, o1, o2;
        gcalc(s0.x, s1.x, s2.x, J0.x, J1.x, o0.x, o1.x, o2.x);
        gcalc(s0.y, s1.y, s2.y, J0.y, J1.y, o0.y, o1.y, o2.y);
        gcalc(s0.z, s1.z, s2.z, J0.z, J1.z, o0.z, o1.z, o2.z);
        gcalc(s0.w, s1.w, s2.w, J0.w, J1.w, o0.w, o1.w, o2.w);
        *(float4*)(d_A + base + a * S) = o0;
        *(float4*)(d_A + NSZ + base + a * S) = o1;
        *(float4*)(d_A + 2 * NSZ + base + a * S) = o2;
    }
}

// ---------------------------------------------------------------------------
// Streaming chain rule + inline adjoint D-box (on d_A) + reg grad +
// Adam(amsgrad), float4 wide.  first -> states implicit zero.  last -> no
// writes, emit reduction partials only.  d_A holds box_W(box_H(g)).
// ---------------------------------------------------------------------------
__global__ void k_chain_adam(const float* __restrict__ y,
                             const float* __restrict__ init,
                             int srcsel, int dstsel, int first,
                             float bc1, float sbc2, int last)
{
    const float* fc_ = flowsel(srcsel, init);
    float*       fn_ = (dstsel == 1) ? d_flowA : d_flowB;
    int q = blockIdx.x * 256 + threadIdx.x;     // float4 cell
    int p4 = q * 4;
    int k4 = q % (DD / 4);
    int line = q / (DD / 4);
    int j = line % WW; int i = line / WW;

    // adjoint D-box via 3 aligned float4 loads per field
    float4 b[3];
#pragma unroll
    for (int f = 0; f < 3; f++) {
        const float* Af = d_A + f * NSZ;
        float4 tm = (k4 > 0)          ? *(const float4*)(Af + p4 - 4) : f4z();
        float4 tc = *(const float4*)(Af + p4);
        float4 tp = (k4 < DD / 4 - 1) ? *(const float4*)(Af + p4 + 4) : f4z();
        // window for output k: sum A[k-4..k+4]; strip = (tm|tc|tp), out[o]=strip[o..o+8]
        b[f] = win9(tm, tc, tp);
    }
    float4 valv = *(const float4*)(d_val + p4);
    float4 yv   = *(const float4*)(y + p4);

    float dI[4];
    {
        const float* bb0 = (const float*)&b[0];
        const float* bb1 = (const float*)&b[1];
        const float* bb2 = (const float*)&b[2];
        const float* vv = (const float*)&valv;
        const float* yy = (const float*)&yv;
#pragma unroll
        for (int o = 0; o < 4; o++)
            dI[o] = -INVN * (bb0[o] + 2.f * vv[o] * bb1[o] + yy[o] * bb2[o]);
    }

    // flow quads for 3 channels
    float4 fv[3];
    fv[0] = *(const float4*)(fc_ + p4);
    fv[1] = *(const float4*)(fc_ + NSZ + p4);
    fv[2] = *(const float4*)(fc_ + 2 * NSZ + p4);

    double acc = 0.0;
#pragma unroll
    for (int ch = 0; ch < 3; ch++) {
        int e = ch * NSZ + p4;
        const float* fc = (const float*)&fv[ch];
        float4 gxv = *(const float4*)(d_gx + e);
        const float* gx = (const float*)&gxv;

        // neighbor quads (zero-guarded)
        float4 wm = (j > 0)      ? *(const float4*)(fc_ + e - DD) : f4z();
        float4 wp = (j < WW - 1) ? *(const float4*)(fc_ + e + DD) : f4z();
        float4 hm = (i > 0)      ? *(const float4*)(fc_ + e - WW * DD) : f4z();
        float4 hp = (i < HH - 1) ? *(const float4*)(fc_ + e + WW * DD) : f4z();
        float dleft  = (k4 > 0)          ? fc_[e - 1] : 0.f;
        float dright = (k4 < DD / 4 - 1) ? fc_[e + 4] : 0.f;

        float4 m4, v4, vh4;
        if (!first) {
            m4  = *(const float4*)(d_m + e);
            v4  = *(const float4*)(d_v + e);
            vh4 = *(const float4*)(d_vh + e);
        } else { m4 = f4z(); v4 = f4z(); vh4 = f4z(); }

        float4 mo, vo, vho, fo;
#pragma unroll
        for (int o = 0; o < 4; o++) {
            int k = 4 * k4 + o;
            float fcc = fc[o];
            float reg = 0.f;
            if (i > 0)      reg += CH_ * (fcc - ((const float*)&hm)[o]);
            if (i < HH - 1) reg += CH_ * (fcc - ((const float*)&hp)[o]);
            if (j > 0)      reg += CW_ * (fcc - ((const float*)&wm)[o]);
            if (j < WW - 1) reg += CW_ * (fcc - ((const float*)&wp)[o]);
            float dl = (o == 0) ? dleft  : fc[o - 1];
            float dr = (o == 3) ? dright : fc[o + 1];
            if (k > 0)      reg += CD_ * (fcc - dl);
            if (k < DD - 1) reg += CD_ * (fcc - dr);
            float g = dI[o] * gx[o] + reg;

            float mm, vv, vh;
            if (first) {
                mm = 0.1f * g; vv = 0.001f * g * g; vh = vv;
            } else {
                mm = 0.9f * ((const float*)&m4)[o] + 0.1f * g;
                vv = 0.999f * ((const float*)&v4)[o] + 0.001f * g * g;
                vh = fmaxf(((const float*)&vh4)[o], vv);
            }
            ((float*)&mo)[o] = mm; ((float*)&vo)[o] = vv; ((float*)&vho)[o] = vh;
            float denom = sqrtf(vh) / sbc2 + 1e-8f;
            float fnew = fcc - 0.1f * (mm / bc1) / denom;
            ((float*)&fo)[o] = fnew;
            if (last) {
                float d = fnew - init[e + o];
                acc += (double)(d * d);
            }
        }
        if (!last) {
            *(float4*)(d_m + e) = mo;
            *(float4*)(d_v + e) = vo;
            *(float4*)(d_vh + e) = vho;
            *(float4*)(fn_ + e) = fo;
        }
    }

    if (last) {
        __shared__ double sd[256];
        sd[threadIdx.x] = acc; __syncthreads();
        for (int s = 128; s > 0; s >>= 1) {
            if (threadIdx.x < s) sd[threadIdx.x] += sd[threadIdx.x + s];
            __syncthreads();
        }
        if (threadIdx.x == 0) d_part[blockIdx.x] = sd[0];
    }
}

// ---------------------------------------------------------------------------
__global__ void k_red2(float* __restrict__ out)
{
    double acc = 0.0;
    for (int e = threadIdx.x; e < NBCHAIN; e += 1024) acc += d_part[e];
    __shared__ double sd[1024];
    sd[threadIdx.x] = acc; __syncthreads();
    for (int s = 512; s > 0; s >>= 1) {
        if (threadIdx.x < s) sd[threadIdx.x] += sd[threadIdx.x + s];
        __syncthreads();
    }
    if (threadIdx.x == 0) out[0] = (float)(sd[0] / (double)N3);
}

// ---------------------------------------------------------------------------
extern "C" void kernel_launch(void* const* d_in, const int* in_sizes, int n_in,
                              void* d_out, int out_size)
{
    (void)in_sizes; (void)n_in; (void)out_size;
    const float* x    = (const float*)d_in[0];
    const float* y    = (const float*)d_in[1];
    const float* init = (const float*)d_in[2];
    float* out = (float*)d_out;

    // W-axis pass params
    const int W_L = WW, W_S = DD, W_nlo4 = DD / 4, W_nch = WW / CHUNK;
    const int W_total = W_nlo4 * W_nch * HH;          // 76800 per field
    // H-axis pass params
    const int H_L = HH, H_S = WW * DD, H_nlo4 = (WW * DD) / 4, H_nch = HH / CHUNK;
    const int H_total = H_nlo4 * H_nch;               // 76800 per field
    const int BOX_BLOCKS = (W_total + 255) / 256;     // 300

    // precompute S_J, S_JJ: boxD -> boxW -> boxH into d_J (2 fields)
    k_boxd_pre<<<HH * WW, DD>>>(y);
    k_box1<<<dim3(BOX_BLOCKS, 2), 256>>>(0, 1, W_L, W_S, W_nlo4, W_nch, W_total);
    k_box1<<<dim3(BOX_BLOCKS, 2), 256>>>(1, 2, H_L, H_S, H_nlo4, H_nch, H_total);

    for (int t = 1; t <= 5; t++) {
        // flow src: t=1 -> init (0); odd t>=3 -> flowA (1); even -> flowB (2)
        int srcsel = (t == 1) ? 0 : ((t & 1) ? 1 : 2);
        int dstsel = (t & 1) ? 2 : 1;   // odd writes flowB, even writes flowA
        float bc1  = (float)(1.0 - pow(0.9, (double)t));
        float sbc2 = sqrtf((float)(1.0 - pow(0.999, (double)t)));

        // forward: warp + vectorized D-box (stores Iw+jacobian), W-box, H-box+gf
        k_boxd_fwd<<<NROWS / LPB, LPB * TPL>>>(x, y, init, srcsel);
        k_box1<<<dim3(BOX_BLOCKS, 3), 256>>>(0, 1, W_L, W_S, W_nlo4, W_nch, W_total); // A->Bf
        k_boxh_gf<<<600, 256>>>();                                                    // Bf,J->A (g)
        // adjoint: H-box, W-box (D-box fused into chain)
        k_box1<<<dim3(BOX_BLOCKS, 3), 256>>>(0, 1, H_L, H_S, H_nlo4, H_nch, H_total); // A->Bf
        k_box1<<<dim3(BOX_BLOCKS, 3), 256>>>(1, 0, W_L, W_S, W_nlo4, W_nch, W_total); // Bf->A
        // chain rule + inline adjoint D-box + reg grad + Adam
        k_chain_adam<<<NBCHAIN, 256>>>(y, init, srcsel, dstsel,
                                       t == 1 ? 1 : 0, bc1, sbc2, t == 5 ? 1 : 0);
    }

    k_red2<<<1, 1024>>>(out);
}

// round 16
// speedup vs baseline: 1.0155x; 1.0155x over previous
#include <cuda_runtime.h>
#include <math.h>

#define HH 160
#define WW 192
#define DD 160
#define NSZ (HH*WW*DD)          // 4,915,200
#define N3  (3*NSZ)             // 14,745,600
#define NROWS (HH*WW)           // 30720
#define CHUNK 16
#define NQ  (NSZ/4)             // 1,228,800 float4 cells
#define NBCHAIN (NQ/256)        // 4800 chain blocks
#define PRE_LPB 8               // lines per block in k_boxd_pre
#define TPL (DD/4)              // threads per line (40)

// ---- scratch (device globals; no allocations allowed) ----
static __device__ float  d_flowA[N3];
static __device__ float  d_flowB[N3];
static __device__ float  d_m[N3];    // Adam m; also precompute ping (2 fields)
static __device__ float  d_v[N3];    // Adam v; also precompute pong (2 fields)
static __device__ float  d_vh[N3];
static __device__ float  d_A[N3];    // ping buffer, 3 fields of NSZ
static __device__ float  d_Bf[N3];   // pong buffer, 3 fields of NSZ
static __device__ float  d_J[2*NSZ]; // S_J, S_JJ (precomputed from y)
static __device__ float  d_val[NSZ]; // warped image Iw (per iter)
static __device__ float  d_gx[N3];   // trilerp jacobian (per iter)
static __device__ double d_part[NBCHAIN];

#define WSF  729.0f
#define INVN (1.0f/4915200.0f)
// reg-gradient coefficients: 2 / (3 * 3*(L-1)*other*other)
#define CH_ (2.0f/43960320.0f)  // 9*159*192*160
#define CW_ (2.0f/44006400.0f)  // 9*160*191*160
#define CD_ (2.0f/43960320.0f)  // 9*160*192*159

__device__ __forceinline__ float4 f4z() { return make_float4(0.f, 0.f, 0.f, 0.f); }
__device__ __forceinline__ float4 operator+(float4 a, float4 b) {
    return make_float4(a.x + b.x, a.y + b.y, a.z + b.z, a.w + b.w);
}
__device__ __forceinline__ float4 operator-(float4 a, float4 b) {
    return make_float4(a.x - b.x, a.y - b.y, a.z - b.z, a.w - b.w);
}

// buffer select: 0=A, 1=Bf, 2=J, 3=m (pre ping), 4=v (pre pong)
__device__ __forceinline__ float* bufsel(int s)
{
    if (s == 0) return d_A;
    if (s == 1) return d_Bf;
    if (s == 2) return d_J;
    if (s == 3) return d_m;
    return d_v;
}

// flow source: 0 = external (init), 1 = flowA, 2 = flowB
__device__ __forceinline__ const float* flowsel(int s, const float* ext)
{
    return (s == 0) ? ext : ((s == 1) ? d_flowA : d_flowB);
}

// ---------------------------------------------------------------------------
// 9-tap window sums of a 12-float strip (tm|tc|tp) -> 4 outputs
// ---------------------------------------------------------------------------
__device__ __forceinline__ float4 win9(float4 tm, float4 tc, float4 tp)
{
    float b0 = tm.x + tm.y + tm.z + tm.w + tc.x + tc.y + tc.z + tc.w + tp.x;
    float b1 = b0 - tm.x + tp.y;
    float b2 = b1 - tm.y + tp.z;
    float b3 = b2 - tm.z + tp.w;
    return make_float4(b0, b1, b2, b3);
}

// ---------------------------------------------------------------------------
// trilinear corner fetch + lerp + gradient wrt coords (zero outside)
// ---------------------------------------------------------------------------
__device__ __forceinline__ void trilerp_all(const float* __restrict__ xv,
    float c0, float c1, float c2,
    float& val, float& gx0, float& gx1, float& gx2)
{
    float l0 = floorf(c0), l1 = floorf(c1), l2 = floorf(c2);
    int i0 = (int)l0, j0 = (int)l1, k0 = (int)l2;
    float f0 = c0 - l0, f1 = c1 - l1, f2 = c2 - l2;
    float v[2][2][2];
#pragma unroll
    for (int a = 0; a < 2; a++) {
        int ii = i0 + a; bool oa = (ii >= 0 && ii < HH);
#pragma unroll
        for (int b = 0; b < 2; b++) {
            int jj = j0 + b; bool ob = oa && (jj >= 0 && jj < WW);
            int base = (ii * WW + jj) * DD;
#pragma unroll
            for (int c = 0; c < 2; c++) {
                int kk = k0 + c; bool oc = ob && (kk >= 0 && kk < DD);
                v[a][b][c] = oc ? __ldg(&xv[base + kk]) : 0.f;
            }
        }
    }
    float u00 = v[0][0][0] * (1.f - f2) + v[0][0][1] * f2;
    float u01 = v[0][1][0] * (1.f - f2) + v[0][1][1] * f2;
    float u10 = v[1][0][0] * (1.f - f2) + v[1][0][1] * f2;
    float u11 = v[1][1][0] * (1.f - f2) + v[1][1][1] * f2;
    float ta = u00 * (1.f - f1) + u01 * f1;
    float tb = u10 * (1.f - f1) + u11 * f1;
    val = ta * (1.f - f0) + tb * f0;
    gx0 = tb - ta;
    gx1 = (1.f - f0) * (u01 - u00) + f0 * (u11 - u10);
    float d00 = v[0][0][1] - v[0][0][0], d01 = v[0][1][1] - v[0][1][0];
    float d10 = v[1][0][1] - v[1][0][0], d11 = v[1][1][1] - v[1][1][0];
    gx2 = (1.f - f0) * ((1.f - f1) * d00 + f1 * d01)
        + f0 * ((1.f - f1) * d10 + f1 * d11);
}

// ---------------------------------------------------------------------------
// warp + products + D-axis box -> d_A[0..2]; also stores Iw -> d_val and
// the trilerp jacobian -> d_gx (consumed by k_chain_adam, no re-gather).
// ---------------------------------------------------------------------------
__global__ void k_boxd_fwd(const float* __restrict__ x, const float* __restrict__ y,
                           const float* __restrict__ init, int sel)
{
    const float* fl = flowsel(sel, init);
    int line = blockIdx.x;
    int i = line / WW, j = line % WW;
    int k = threadIdx.x;
    int p = line * DD + k;

    float c0 = (float)i + fl[p];
    float c1 = (float)j + fl[NSZ + p];
    float c2 = (float)k + fl[2 * NSZ + p];
    float Iw, g0, g1, g2;
    trilerp_all(x, c0, c1, c2, Iw, g0, g1, g2);
    float yy = y[p];

    d_val[p] = Iw;
    d_gx[p] = g0; d_gx[NSZ + p] = g1; d_gx[2 * NSZ + p] = g2;

    __shared__ float s[3][DD + 8];
    s[0][4 + k] = Iw;
    s[1][4 + k] = Iw * Iw;
    s[2][4 + k] = Iw * yy;
    if (k < 4) {
        s[0][k] = 0.f; s[1][k] = 0.f; s[2][k] = 0.f;
        s[0][DD + 4 + k] = 0.f; s[1][DD + 4 + k] = 0.f; s[2][DD + 4 + k] = 0.f;
    }
    __syncthreads();
    float r0 = 0.f, r1 = 0.f, r2 = 0.f;
#pragma unroll
    for (int t = 0; t < 9; t++) {
        r0 += s[0][k + t]; r1 += s[1][k + t]; r2 += s[2][k + t];
    }
    d_A[p] = r0; d_A[NSZ + p] = r1; d_A[2 * NSZ + p] = r2;
}

// ---------------------------------------------------------------------------
// D-axis box of (y, y*y) -> d_m[0..1]  (precompute ping; vectorized win9)
// 8 lines per block, each thread owns 4 consecutive k.
// ---------------------------------------------------------------------------
__global__ void k_boxd_pre(const float* __restrict__ y)
{
    int tid = threadIdx.x;              // 0..319
    int sub = tid / TPL;
    int l   = tid % TPL;
    int line = blockIdx.x * PRE_LPB + sub;
    int k0 = l * 4;
    int p = line * DD + k0;

    __shared__ float s[2][PRE_LPB][DD + 8];
    if (l < 4) {
        s[0][sub][l] = 0.f; s[1][sub][l] = 0.f;
        s[0][sub][DD + 4 + l] = 0.f; s[1][sub][DD + 4 + l] = 0.f;
    }
    float4 yv = *(const float4*)(y + p);
    *(float4*)&s[0][sub][4 + k0] = yv;
    *(float4*)&s[1][sub][4 + k0] = make_float4(yv.x * yv.x, yv.y * yv.y,
                                               yv.z * yv.z, yv.w * yv.w);
    __syncthreads();
#pragma unroll
    for (int f = 0; f < 2; f++) {
        float4 q0 = *(const float4*)&s[f][sub][k0];
        float4 q1 = *(const float4*)&s[f][sub][k0 + 4];
        float4 q2 = *(const float4*)&s[f][sub][k0 + 8];
        *(float4*)(d_m + f * NSZ + p) = win9(q0, q1, q2);
    }
}

// ---------------------------------------------------------------------------
// Strided-axis box, one field per thread (field = blockIdx.y), sliding
// window with software pipelining (3 batches of 5 steps, 10 loads in flight).
// ---------------------------------------------------------------------------
__global__ void k_box1(int ssel, int dsel, int L, int S, int nlo4, int nchunk,
                       int total)
{
    int tid = blockIdx.x * 256 + threadIdx.x;
    if (tid >= total) return;
    int f = blockIdx.y;
    int lo4 = tid % nlo4;
    int rest = tid / nlo4;
    int chunk = rest % nchunk;
    int hi = rest / nchunk;

    const float* __restrict__ in = bufsel(ssel) + f * NSZ;
    float* __restrict__ out = bufsel(dsel) + f * NSZ;

    int c0 = chunk * CHUNK;
    int base = hi * L * S + lo4 * 4;

    // initial 9-tap window: all loads independent
    float4 w[9];
#pragma unroll
    for (int t = 0; t < 9; t++) {
        int a = c0 - 4 + t;
        w[t] = ((unsigned)a < (unsigned)L) ? *(const float4*)(in + base + a * S) : f4z();
    }
    float4 s = ((((((((w[0] + w[1]) + w[2]) + w[3]) + w[4]) + w[5]) + w[6]) + w[7]) + w[8]);
    *(float4*)(out + base + c0 * S) = s;

    // 15 sliding steps in 3 batches of 5 (10 loads in flight per batch)
#pragma unroll
    for (int bb = 0; bb < 3; bb++) {
        float4 vin[5], vout[5];
#pragma unroll
        for (int u = 0; u < 5; u++) {
            int o = bb * 5 + u + 1;
            int ain = c0 + o + 4, aout = c0 + o - 5;
            vin[u]  = ((unsigned)ain < (unsigned)L) ? *(const float4*)(in + base + ain * S)  : f4z();
            vout[u] = (aout >= 0)                   ? *(const float4*)(in + base + aout * S) : f4z();
        }
#pragma unroll
        for (int u = 0; u < 5; u++) {
            int o = bb * 5 + u + 1;
            s = s + vin[u] - vout[u];
            *(float4*)(out + base + (c0 + o) * S) = s;
        }
    }
}

// ---------------------------------------------------------------------------
// per-lane NCC partials from full window sums
// ---------------------------------------------------------------------------
__device__ __forceinline__ void gcalc(float SI, float SII, float SIJ,
                                      float SJ, float SJJ,
                                      float& gI, float& gII, float& gIJ)
{
    float uI = SI / WSF, uJ = SJ / WSF;
    float cross = SIJ - uJ * SI - uI * SJ + uI * uJ * WSF;
    float Iv = SII - 2.f * uI * SI + uI * uI * WSF;
    float Jv = SJJ - 2.f * uJ * SJ + uJ * uJ * WSF;
    float Dn = Iv * Jv + 1e-5f;
    float t0 = cross / Dn;
    float q  = 2.f * t0;
    float r  = t0 * t0 * Jv;
    gI  = -q * uJ + 2.f * r * uI;
    gII = -r;
    gIJ = q;
}

// ---------------------------------------------------------------------------
// Forward H-axis box fused with gf: completes window sums in registers and
// emits g-fields.  in: d_Bf (D,W-boxed), d_J  ->  out: d_A = (gI,gII,gIJ)
// ---------------------------------------------------------------------------
__global__ void k_boxh_gf(void)
{
    const int nlo4 = (WW * DD) / 4;   // 7680
    const int nch  = HH / 8;          // 20
    int tid = blockIdx.x * 256 + threadIdx.x;
    if (tid >= nlo4 * nch) return;
    int lo4 = tid % nlo4;
    int chunk = tid / nlo4;
    int c0 = chunk * 8;
    int base = lo4 * 4;
    const int S = WW * DD;

    float4 s0 = f4z(), s1 = f4z(), s2 = f4z();
#pragma unroll
    for (int t = -4; t <= 4; t++) {
        int a = c0 + t;
        if ((unsigned)a < (unsigned)HH) {
            s0 = s0 + *(const float4*)(d_Bf + base + a * S);
            s1 = s1 + *(const float4*)(d_Bf + NSZ + base + a * S);
            s2 = s2 + *(const float4*)(d_Bf + 2 * NSZ + base + a * S);
        }
    }

#pragma unroll
    for (int o = 0; o < 8; o++) {
        int a = c0 + o;
        if (o > 0) {
            int ain = a + 4, aout = a - 5;
            if ((unsigned)ain < (unsigned)HH) {
                s0 = s0 + *(const float4*)(d_Bf + base + ain * S);
                s1 = s1 + *(const float4*)(d_Bf + NSZ + base + ain * S);
                s2 = s2 + *(const float4*)(d_Bf + 2 * NSZ + base + ain * S);
            }
            if (aout >= 0) {
                s0 = s0 - *(const float4*)(d_Bf + base + aout * S);
                s1 = s1 - *(const float4*)(d_Bf + NSZ + base + aout * S);
                s2 = s2 - *(const float4*)(d_Bf + 2 * NSZ + base + aout * S);
            }
        }
        float4 J0 = *(const float4*)(d_J + base + a * S);
        float4 J1 = *(const float4*)(d_J + NSZ + base + a * S);
        float4 o0, o1, o2;
        gcalc(s0.x, s1.x, s2.x, J0.x, J1.x, o0.x, o1.x, o2.x);
        gcalc(s0.y, s1.y, s2.y, J0.y, J1.y, o0.y, o1.y, o2.y);
        gcalc(s0.z, s1.z, s2.z, J0.z, J1.z, o0.z, o1.z, o2.z);
        gcalc(s0.w, s1.w, s2.w, J0.w, J1.w, o0.w, o1.w, o2.w);
        *(float4*)(d_A + base + a * S) = o0;
        *(float4*)(d_A + NSZ + base + a * S) = o1;
        *(float4*)(d_A + 2 * NSZ + base + a * S) = o2;
    }
}

// ---------------------------------------------------------------------------
// Streaming chain rule + inline adjoint D-box (on d_A) + reg grad +
// Adam(amsgrad), float4 wide.  first -> states implicit zero.  last -> no
// writes, emit reduction partials only.  d_A holds box_W(box_H(g)).
// ---------------------------------------------------------------------------
__global__ void k_chain_adam(const float* __restrict__ y,
                             const float* __restrict__ init,
                             int srcsel, int dstsel, int first,
                             float bc1, float sbc2, int last)
{
    const float* fc_ = flowsel(srcsel, init);
    float*       fn_ = (dstsel == 1) ? d_flowA : d_flowB;
    int q = blockIdx.x * 256 + threadIdx.x;     // float4 cell
    int p4 = q * 4;
    int k4 = q % (DD / 4);
    int line = q / (DD / 4);
    int j = line % WW; int i = line / WW;

    // adjoint D-box via 3 aligned float4 loads per field
    float4 b[3];
#pragma unroll
    for (int f = 0; f < 3; f++) {
        const float* Af = d_A + f * NSZ;
        float4 tm = (k4 > 0)          ? *(const float4*)(Af + p4 - 4) : f4z();
        float4 tc = *(const float4*)(Af + p4);
        float4 tp = (k4 < DD / 4 - 1) ? *(const float4*)(Af + p4 + 4) : f4z();
        b[f] = win9(tm, tc, tp);
    }
    float4 valv = *(const float4*)(d_val + p4);
    float4 yv   = *(const float4*)(y + p4);

    float dI[4];
    {
        const float* bb0 = (const float*)&b[0];
        const float* bb1 = (const float*)&b[1];
        const float* bb2 = (const float*)&b[2];
        const float* vv = (const float*)&valv;
        const float* yy = (const float*)&yv;
#pragma unroll
        for (int o = 0; o < 4; o++)
            dI[o] = -INVN * (bb0[o] + 2.f * vv[o] * bb1[o] + yy[o] * bb2[o]);
    }

    // flow quads for 3 channels
    float4 fv[3];
    fv[0] = *(const float4*)(fc_ + p4);
    fv[1] = *(const float4*)(fc_ + NSZ + p4);
    fv[2] = *(const float4*)(fc_ + 2 * NSZ + p4);

    double acc = 0.0;
#pragma unroll
    for (int ch = 0; ch < 3; ch++) {
        int e = ch * NSZ + p4;
        const float* fc = (const float*)&fv[ch];
        float4 gxv = *(const float4*)(d_gx + e);
        const float* gx = (const float*)&gxv;

        // neighbor quads (zero-guarded)
        float4 wm = (j > 0)      ? *(const float4*)(fc_ + e - DD) : f4z();
        float4 wp = (j < WW - 1) ? *(const float4*)(fc_ + e + DD) : f4z();
        float4 hm = (i > 0)      ? *(const float4*)(fc_ + e - WW * DD) : f4z();
        float4 hp = (i < HH - 1) ? *(const float4*)(fc_ + e + WW * DD) : f4z();
        float dleft  = (k4 > 0)          ? fc_[e - 1] : 0.f;
        float dright = (k4 < DD / 4 - 1) ? fc_[e + 4] : 0.f;

        float4 m4, v4, vh4;
        if (!first) {
            m4  = *(const float4*)(d_m + e);
            v4  = *(const float4*)(d_v + e);
            vh4 = *(const float4*)(d_vh + e);
        } else { m4 = f4z(); v4 = f4z(); vh4 = f4z(); }

        float4 mo, vo, vho, fo;
#pragma unroll
        for (int o = 0; o < 4; o++) {
            int k = 4 * k4 + o;
            float fcc = fc[o];
            float reg = 0.f;
            if (i > 0)      reg += CH_ * (fcc - ((const float*)&hm)[o]);
            if (i < HH - 1) reg += CH_ * (fcc - ((const float*)&hp)[o]);
            if (j > 0)      reg += CW_ * (fcc - ((const float*)&wm)[o]);
            if (j < WW - 1) reg += CW_ * (fcc - ((const float*)&wp)[o]);
            float dl = (o == 0) ? dleft  : fc[o - 1];
            float dr = (o == 3) ? dright : fc[o + 1];
            if (k > 0)      reg += CD_ * (fcc - dl);
            if (k < DD - 1) reg += CD_ * (fcc - dr);
            float g = dI[o] * gx[o] + reg;

            float mm, vv, vh;
            if (first) {
                mm = 0.1f * g; vv = 0.001f * g * g; vh = vv;
            } else {
                mm = 0.9f * ((const float*)&m4)[o] + 0.1f * g;
                vv = 0.999f * ((const float*)&v4)[o] + 0.001f * g * g;
                vh = fmaxf(((const float*)&vh4)[o], vv);
            }
            ((float*)&mo)[o] = mm; ((float*)&vo)[o] = vv; ((float*)&vho)[o] = vh;
            float denom = sqrtf(vh) / sbc2 + 1e-8f;
            float fnew = fcc - 0.1f * (mm / bc1) / denom;
            ((float*)&fo)[o] = fnew;
            if (last) {
                float d = fnew - init[e + o];
                acc += (double)(d * d);
            }
        }
        if (!last) {
            *(float4*)(d_m + e) = mo;
            *(float4*)(d_v + e) = vo;
            *(float4*)(d_vh + e) = vho;
            *(float4*)(fn_ + e) = fo;
        }
    }

    if (last) {
        __shared__ double sd[256];
        sd[threadIdx.x] = acc; __syncthreads();
        for (int s = 128; s > 0; s >>= 1) {
            if (threadIdx.x < s) sd[threadIdx.x] += sd[threadIdx.x + s];
            __syncthreads();
        }
        if (threadIdx.x == 0) d_part[blockIdx.x] = sd[0];
    }
}

// ---------------------------------------------------------------------------
__global__ void k_red2(float* __restrict__ out)
{
    double acc = 0.0;
    for (int e = threadIdx.x; e < NBCHAIN; e += 1024) acc += d_part[e];
    __shared__ double sd[1024];
    sd[threadIdx.x] = acc; __syncthreads();
    for (int s = 512; s > 0; s >>= 1) {
        if (threadIdx.x < s) sd[threadIdx.x] += sd[threadIdx.x + s];
        __syncthreads();
    }
    if (threadIdx.x == 0) out[0] = (float)(sd[0] / (double)N3);
}

// ---------------------------------------------------------------------------
extern "C" void kernel_launch(void* const* d_in, const int* in_sizes, int n_in,
                              void* d_out, int out_size)
{
    (void)in_sizes; (void)n_in; (void)out_size;
    const float* x    = (const float*)d_in[0];
    const float* y    = (const float*)d_in[1];
    const float* init = (const float*)d_in[2];
    float* out = (float*)d_out;

    // one-time resources (resource setup only; enqueued work is identical
    // on every call, so determinism/graph requirements hold)
    static cudaStream_t s2 = nullptr;
    static cudaEvent_t evFork = nullptr, evJoin = nullptr;
    if (s2 == nullptr) {
        cudaStreamCreateWithFlags(&s2, cudaStreamNonBlocking);
        cudaEventCreateWithFlags(&evFork, cudaEventDisableTiming);
        cudaEventCreateWithFlags(&evJoin, cudaEventDisableTiming);
    }

    // W-axis pass params
    const int W_L = WW, W_S = DD, W_nlo4 = DD / 4, W_nch = WW / CHUNK;
    const int W_total = W_nlo4 * W_nch * HH;          // 76800 per field
    // H-axis pass params
    const int H_L = HH, H_S = WW * DD, H_nlo4 = (WW * DD) / 4, H_nch = HH / CHUNK;
    const int H_total = H_nlo4 * H_nch;               // 76800 per field
    const int BOX_BLOCKS = (W_total + 255) / 256;     // 300

    // ---- fork: J precompute on s2 (temporaries: d_m -> d_v -> d_J),
    //      overlapped with iteration-1 forward on the main stream ----
    cudaEventRecord(evFork, 0);
    cudaStreamWaitEvent(s2, evFork, 0);
    k_boxd_pre<<<NROWS / PRE_LPB, PRE_LPB * TPL, 0, s2>>>(y);
    k_box1<<<dim3(BOX_BLOCKS, 2), 256, 0, s2>>>(3, 4, W_L, W_S, W_nlo4, W_nch, W_total); // m->v
    k_box1<<<dim3(BOX_BLOCKS, 2), 256, 0, s2>>>(4, 2, H_L, H_S, H_nlo4, H_nch, H_total); // v->J
    cudaEventRecord(evJoin, s2);

    for (int t = 1; t <= 5; t++) {
        // flow src: t=1 -> init (0); odd t>=3 -> flowA (1); even -> flowB (2)
        int srcsel = (t == 1) ? 0 : ((t & 1) ? 1 : 2);
        int dstsel = (t & 1) ? 2 : 1;   // odd writes flowB, even writes flowA
        float bc1  = (float)(1.0 - pow(0.9, (double)t));
        float sbc2 = sqrtf((float)(1.0 - pow(0.999, (double)t)));

        // forward: warp + D-box (fused, stores Iw+jacobian), W-box
        k_boxd_fwd<<<HH * WW, DD>>>(x, y, init, srcsel);
        k_box1<<<dim3(BOX_BLOCKS, 3), 256>>>(0, 1, W_L, W_S, W_nlo4, W_nch, W_total); // A->Bf
        // join: first consumer of d_J (and of d_m/d_v staying free for chain)
        if (t == 1) cudaStreamWaitEvent(0, evJoin, 0);
        k_boxh_gf<<<600, 256>>>();                                                    // Bf,J->A (g)
        // adjoint: H-box, W-box (D-box fused into chain)
        k_box1<<<dim3(BOX_BLOCKS, 3), 256>>>(0, 1, H_L, H_S, H_nlo4, H_nch, H_total); // A->Bf
        k_box1<<<dim3(BOX_BLOCKS, 3), 256>>>(1, 0, W_L, W_S, W_nlo4, W_nch, W_total); // Bf->A
        // chain rule + inline adjoint D-box + reg grad + Adam
        k_chain_adam<<<NBCHAIN, 256>>>(y, init, srcsel, dstsel,
                                       t == 1 ? 1 : 0, bc1, sbc2, t == 5 ? 1 : 0);
    }

    k_red2<<<1, 1024>>>(out);
}

// round 17
// speedup vs baseline: 1.0268x; 1.0111x over previous
#include <cuda_runtime.h>
#include <math.h>

#define HH 160
#define WW 192
#define DD 160
#define NSZ (HH*WW*DD)          // 4,915,200
#define N3  (3*NSZ)             // 14,745,600
#define CHUNK 16
#define NQ  (NSZ/4)             // 1,228,800 float4 cells
#define NBCHAIN (NQ/256)        // 4800 chain blocks

// ---- scratch (device globals; no allocations allowed) ----
static __device__ float  d_flowA[N3];
static __device__ float  d_flowB[N3];
static __device__ float  d_m[N3];
static __device__ float  d_v[N3];
static __device__ float  d_vh[N3];
static __device__ float  d_A[N3];     // ping buffer, 3 fields of NSZ
static __device__ float  d_Bf[N3];    // pong buffer, 3 fields of NSZ
static __device__ float  d_J[2*NSZ];  // S_J, S_JJ (precomputed from y)
static __device__ float  d_val[NSZ];  // warped image Iw (per iter)
static __device__ float  d_gx[N3];    // trilerp jacobian (per iter)
static __device__ double d_part[NBCHAIN];

#define WSF  729.0f
#define INVN (1.0f/4915200.0f)
// reg-gradient coefficients: 2 / (3 * 3*(L-1)*other*other)
#define CH_ (2.0f/43960320.0f)  // 9*159*192*160
#define CW_ (2.0f/44006400.0f)  // 9*160*191*160
#define CD_ (2.0f/43960320.0f)  // 9*160*192*159

__device__ __forceinline__ float4 f4z() { return make_float4(0.f, 0.f, 0.f, 0.f); }
__device__ __forceinline__ float4 operator+(float4 a, float4 b) {
    return make_float4(a.x + b.x, a.y + b.y, a.z + b.z, a.w + b.w);
}
__device__ __forceinline__ float4 operator-(float4 a, float4 b) {
    return make_float4(a.x - b.x, a.y - b.y, a.z - b.z, a.w - b.w);
}

__device__ __forceinline__ float* bufsel(int s)
{
    return (s == 0) ? d_A : ((s == 1) ? d_Bf : d_J);
}

// flow source: 0 = external (init), 1 = flowA, 2 = flowB
__device__ __forceinline__ const float* flowsel(int s, const float* ext)
{
    return (s == 0) ? ext : ((s == 1) ? d_flowA : d_flowB);
}

// ---------------------------------------------------------------------------
// trilinear corner fetch + lerp + gradient wrt coords (zero outside)
// ---------------------------------------------------------------------------
__device__ __forceinline__ void trilerp_all(const float* __restrict__ xv,
    float c0, float c1, float c2,
    float& val, float& gx0, float& gx1, float& gx2)
{
    float l0 = floorf(c0), l1 = floorf(c1), l2 = floorf(c2);
    int i0 = (int)l0, j0 = (int)l1, k0 = (int)l2;
    float f0 = c0 - l0, f1 = c1 - l1, f2 = c2 - l2;
    float v[2][2][2];
#pragma unroll
    for (int a = 0; a < 2; a++) {
        int ii = i0 + a; bool oa = (ii >= 0 && ii < HH);
#pragma unroll
        for (int b = 0; b < 2; b++) {
            int jj = j0 + b; bool ob = oa && (jj >= 0 && jj < WW);
            int base = (ii * WW + jj) * DD;
#pragma unroll
            for (int c = 0; c < 2; c++) {
                int kk = k0 + c; bool oc = ob && (kk >= 0 && kk < DD);
                v[a][b][c] = oc ? __ldg(&xv[base + kk]) : 0.f;
            }
        }
    }
    float u00 = v[0][0][0] * (1.f - f2) + v[0][0][1] * f2;
    float u01 = v[0][1][0] * (1.f - f2) + v[0][1][1] * f2;
    float u10 = v[1][0][0] * (1.f - f2) + v[1][0][1] * f2;
    float u11 = v[1][1][0] * (1.f - f2) + v[1][1][1] * f2;
    float ta = u00 * (1.f - f1) + u01 * f1;
    float tb = u10 * (1.f - f1) + u11 * f1;
    val = ta * (1.f - f0) + tb * f0;
    gx0 = tb - ta;
    gx1 = (1.f - f0) * (u01 - u00) + f0 * (u11 - u10);
    float d00 = v[0][0][1] - v[0][0][0], d01 = v[0][1][1] - v[0][1][0];
    float d10 = v[1][0][1] - v[1][0][0], d11 = v[1][1][1] - v[1][1][0];
    gx2 = (1.f - f0) * ((1.f - f1) * d00 + f1 * d01)
        + f0 * ((1.f - f1) * d10 + f1 * d11);
}

// ---------------------------------------------------------------------------
// warp + products + D-axis box -> d_A[0..2]; also stores Iw -> d_val and
// the trilerp jacobian -> d_gx (consumed by k_chain_adam, no re-gather).
// ---------------------------------------------------------------------------
__global__ void k_boxd_fwd(const float* __restrict__ x, const float* __restrict__ y,
                           const float* __restrict__ init, int sel)
{
    const float* fl = flowsel(sel, init);
    int line = blockIdx.x;
    int i = line / WW, j = line % WW;
    int k = threadIdx.x;
    int p = line * DD + k;

    float c0 = (float)i + fl[p];
    float c1 = (float)j + fl[NSZ + p];
    float c2 = (float)k + fl[2 * NSZ + p];
    float Iw, g0, g1, g2;
    trilerp_all(x, c0, c1, c2, Iw, g0, g1, g2);
    float yy = y[p];

    d_val[p] = Iw;
    d_gx[p] = g0; d_gx[NSZ + p] = g1; d_gx[2 * NSZ + p] = g2;

    __shared__ float s[3][DD + 8];
    s[0][4 + k] = Iw;
    s[1][4 + k] = Iw * Iw;
    s[2][4 + k] = Iw * yy;
    if (k < 4) {
        s[0][k] = 0.f; s[1][k] = 0.f; s[2][k] = 0.f;
        s[0][DD + 4 + k] = 0.f; s[1][DD + 4 + k] = 0.f; s[2][DD + 4 + k] = 0.f;
    }
    __syncthreads();
    float r0 = 0.f, r1 = 0.f, r2 = 0.f;
#pragma unroll
    for (int t = 0; t < 9; t++) {
        r0 += s[0][k + t]; r1 += s[1][k + t]; r2 += s[2][k + t];
    }
    d_A[p] = r0; d_A[NSZ + p] = r1; d_A[2 * NSZ + p] = r2;
}

// D-axis box of (y, y*y) -> d_A[0..1]
__global__ void k_boxd_pre(const float* __restrict__ y)
{
    int line = blockIdx.x;
    int k = threadIdx.x;
    int p = line * DD + k;
    float yy = y[p];
    __shared__ float s[2][DD + 8];
    s[0][4 + k] = yy; s[1][4 + k] = yy * yy;
    if (k < 4) {
        s[0][k] = 0.f; s[1][k] = 0.f;
        s[0][DD + 4 + k] = 0.f; s[1][DD + 4 + k] = 0.f;
    }
    __syncthreads();
    float r0 = 0.f, r1 = 0.f;
#pragma unroll
    for (int t = 0; t < 9; t++) { r0 += s[0][k + t]; r1 += s[1][k + t]; }
    d_A[p] = r0; d_A[NSZ + p] = r1;
}

// ---------------------------------------------------------------------------
// Strided-axis box, one field per thread (field = blockIdx.y), sliding
// window with software pipelining (3 batches of 5 steps, 10 loads in flight).
// ---------------------------------------------------------------------------
__global__ void k_box1(int ssel, int dsel, int L, int S, int nlo4, int nchunk,
                       int total)
{
    int tid = blockIdx.x * 256 + threadIdx.x;
    if (tid >= total) return;
    int f = blockIdx.y;
    int lo4 = tid % nlo4;
    int rest = tid / nlo4;
    int chunk = rest % nchunk;
    int hi = rest / nchunk;

    const float* __restrict__ in = bufsel(ssel) + f * NSZ;
    float* __restrict__ out = bufsel(dsel) + f * NSZ;

    int c0 = chunk * CHUNK;
    int base = hi * L * S + lo4 * 4;

    // initial 9-tap window: all loads independent
    float4 w[9];
#pragma unroll
    for (int t = 0; t < 9; t++) {
        int a = c0 - 4 + t;
        w[t] = ((unsigned)a < (unsigned)L) ? *(const float4*)(in + base + a * S) : f4z();
    }
    float4 s = ((((((((w[0] + w[1]) + w[2]) + w[3]) + w[4]) + w[5]) + w[6]) + w[7]) + w[8]);
    *(float4*)(out + base + c0 * S) = s;

    // 15 sliding steps in 3 batches of 5 (10 loads in flight per batch)
#pragma unroll
    for (int bb = 0; bb < 3; bb++) {
        float4 vin[5], vout[5];
#pragma unroll
        for (int u = 0; u < 5; u++) {
            int o = bb * 5 + u + 1;
            int ain = c0 + o + 4, aout = c0 + o - 5;
            vin[u]  = ((unsigned)ain < (unsigned)L) ? *(const float4*)(in + base + ain * S)  : f4z();
            vout[u] = (aout >= 0)                   ? *(const float4*)(in + base + aout * S) : f4z();
        }
#pragma unroll
        for (int u = 0; u < 5; u++) {
            int o = bb * 5 + u + 1;
            s = s + vin[u] - vout[u];
            *(float4*)(out + base + (c0 + o) * S) = s;
        }
    }
}

// ---------------------------------------------------------------------------
// per-lane NCC partials from full window sums
// ---------------------------------------------------------------------------
__device__ __forceinline__ void gcalc(float SI, float SII, float SIJ,
                                      float SJ, float SJJ,
                                      float& gI, float& gII, float& gIJ)
{
    float uI = SI / WSF, uJ = SJ / WSF;
    float cross = SIJ - uJ * SI - uI * SJ + uI * uJ * WSF;
    float Iv = SII - 2.f * uI * SI + uI * uI * WSF;
    float Jv = SJJ - 2.f * uJ * SJ + uJ * uJ * WSF;
    float Dn = Iv * Jv + 1e-5f;
    float t0 = cross / Dn;
    float q  = 2.f * t0;
    float r  = t0 * t0 * Jv;
    gI  = -q * uJ + 2.f * r * uI;
    gII = -r;
    gIJ = q;
}

// ---------------------------------------------------------------------------
// Forward H-axis box fused with gf: completes window sums in registers and
// emits g-fields.  in: d_Bf (D,W-boxed), d_J  ->  out: d_A = (gI,gII,gIJ)
// ---------------------------------------------------------------------------
__global__ void k_boxh_gf(void)
{
    const int nlo4 = (WW * DD) / 4;   // 7680
    const int nch  = HH / 8;          // 20
    int tid = blockIdx.x * 256 + threadIdx.x;
    if (tid >= nlo4 * nch) return;
    int lo4 = tid % nlo4;
    int chunk = tid / nlo4;
    int c0 = chunk * 8;
    int base = lo4 * 4;
    const int S = WW * DD;

    float4 s0 = f4z(), s1 = f4z(), s2 = f4z();
#pragma unroll
    for (int t = -4; t <= 4; t++) {
        int a = c0 + t;
        if ((unsigned)a < (unsigned)HH) {
            s0 = s0 + *(const float4*)(d_Bf + base + a * S);
            s1 = s1 + *(const float4*)(d_Bf + NSZ + base + a * S);
            s2 = s2 + *(const float4*)(d_Bf + 2 * NSZ + base + a * S);
        }
    }

#pragma unroll
    for (int o = 0; o < 8; o++) {
        int a = c0 + o;
        if (o > 0) {
            int ain = a + 4, aout = a - 5;
            if ((unsigned)ain < (unsigned)HH) {
                s0 = s0 + *(const float4*)(d_Bf + base + ain * S);
                s1 = s1 + *(const float4*)(d_Bf + NSZ + base + ain * S);
                s2 = s2 + *(const float4*)(d_Bf + 2 * NSZ + base + ain * S);
            }
            if (aout >= 0) {
                s0 = s0 - *(const float4*)(d_Bf + base + aout * S);
                s1 = s1 - *(const float4*)(d_Bf + NSZ + base + aout * S);
                s2 = s2 - *(const float4*)(d_Bf + 2 * NSZ + base + aout * S);
            }
        }
        float4 J0 = *(const float4*)(d_J + base + a * S);
        float4 J1 = *(const float4*)(d_J + NSZ + base + a * S);
        float4 o0, o1, o2;
        gcalc(s0.x, s1.x, s2.x, J0.x, J1.x, o0.x, o1.x, o2.x);
        gcalc(s0.y, s1.y, s2.y, J0.y, J1.y, o0.y, o1.y, o2.y);
        gcalc(s0.z, s1.z, s2.z, J0.z, J1.z, o0.z, o1.z, o2.z);
        gcalc(s0.w, s1.w, s2.w, J0.w, J1.w, o0.w, o1.w, o2.w);
        *(float4*)(d_A + base + a * S) = o0;
        *(float4*)(d_A + NSZ + base + a * S) = o1;
        *(float4*)(d_A + 2 * NSZ + base + a * S) = o2;
    }
}

// ---------------------------------------------------------------------------
// 9-tap window sums of a 12-float strip (tm|tc|tp) -> 4 outputs
// ---------------------------------------------------------------------------
__device__ __forceinline__ float4 win9(float4 tm, float4 tc, float4 tp)
{
    float b0 = tm.x + tm.y + tm.z + tm.w + tc.x + tc.y + tc.z + tc.w + tp.x;
    float b1 = b0 - tm.x + tp.y;
    float b2 = b1 - tm.y + tp.z;
    float b3 = b2 - tm.z + tp.w;
    return make_float4(b0, b1, b2, b3);
}

// ---------------------------------------------------------------------------
// Streaming chain rule + inline adjoint D-box (on d_A) + reg grad +
// Adam(amsgrad), float4 wide.  first -> states implicit zero.  last -> no
// writes, emit reduction partials only.  d_A holds box_W(box_H(g)).
// ---------------------------------------------------------------------------
__global__ void k_chain_adam(const float* __restrict__ y,
                             const float* __restrict__ init,
                             int srcsel, int dstsel, int first,
                             float bc1, float sbc2, int last)
{
    const float* fc_ = flowsel(srcsel, init);
    float*       fn_ = (dstsel == 1) ? d_flowA : d_flowB;
    int q = blockIdx.x * 256 + threadIdx.x;     // float4 cell
    int p4 = q * 4;
    int k4 = q % (DD / 4);
    int line = q / (DD / 4);
    int j = line % WW; int i = line / WW;

    // adjoint D-box via 3 aligned float4 loads per field
    float4 b[3];
#pragma unroll
    for (int f = 0; f < 3; f++) {
        const float* Af = d_A + f * NSZ;
        float4 tm = (k4 > 0)          ? *(const float4*)(Af + p4 - 4) : f4z();
        float4 tc = *(const float4*)(Af + p4);
        float4 tp = (k4 < DD / 4 - 1) ? *(const float4*)(Af + p4 + 4) : f4z();
        b[f] = win9(tm, tc, tp);
    }
    float4 valv = *(const float4*)(d_val + p4);
    float4 yv   = *(const float4*)(y + p4);

    float dI[4];
    {
        const float* bb0 = (const float*)&b[0];
        const float* bb1 = (const float*)&b[1];
        const float* bb2 = (const float*)&b[2];
        const float* vv = (const float*)&valv;
        const float* yy = (const float*)&yv;
#pragma unroll
        for (int o = 0; o < 4; o++)
            dI[o] = -INVN * (bb0[o] + 2.f * vv[o] * bb1[o] + yy[o] * bb2[o]);
    }

    // flow quads for 3 channels
    float4 fv[3];
    fv[0] = *(const float4*)(fc_ + p4);
    fv[1] = *(const float4*)(fc_ + NSZ + p4);
    fv[2] = *(const float4*)(fc_ + 2 * NSZ + p4);

    double acc = 0.0;
#pragma unroll
    for (int ch = 0; ch < 3; ch++) {
        int e = ch * NSZ + p4;
        const float* fc = (const float*)&fv[ch];
        float4 gxv = *(const float4*)(d_gx + e);
        const float* gx = (const float*)&gxv;

        // neighbor quads (zero-guarded)
        float4 wm = (j > 0)      ? *(const float4*)(fc_ + e - DD) : f4z();
        float4 wp = (j < WW - 1) ? *(const float4*)(fc_ + e + DD) : f4z();
        float4 hm = (i > 0)      ? *(const float4*)(fc_ + e - WW * DD) : f4z();
        float4 hp = (i < HH - 1) ? *(const float4*)(fc_ + e + WW * DD) : f4z();
        float dleft  = (k4 > 0)          ? fc_[e - 1] : 0.f;
        float dright = (k4 < DD / 4 - 1) ? fc_[e + 4] : 0.f;

        float4 m4, v4, vh4;
        if (!first) {
            m4  = *(const float4*)(d_m + e);
            v4  = *(const float4*)(d_v + e);
            vh4 = *(const float4*)(d_vh + e);
        } else { m4 = f4z(); v4 = f4z(); vh4 = f4z(); }

        float4 mo, vo, vho, fo;
#pragma unroll
        for (int o = 0; o < 4; o++) {
            int k = 4 * k4 + o;
            float fcc = fc[o];
            float reg = 0.f;
            if (i > 0)      reg += CH_ * (fcc - ((const float*)&hm)[o]);
            if (i < HH - 1) reg += CH_ * (fcc - ((const float*)&hp)[o]);
            if (j > 0)      reg += CW_ * (fcc - ((const float*)&wm)[o]);
            if (j < WW - 1) reg += CW_ * (fcc - ((const float*)&wp)[o]);
            float dl = (o == 0) ? dleft  : fc[o - 1];
            float dr = (o == 3) ? dright : fc[o + 1];
            if (k > 0)      reg += CD_ * (fcc - dl);
            if (k < DD - 1) reg += CD_ * (fcc - dr);
            float g = dI[o] * gx[o] + reg;

            float mm, vv, vh;
            if (first) {
                mm = 0.1f * g; vv = 0.001f * g * g; vh = vv;
            } else {
                mm = 0.9f * ((const float*)&m4)[o] + 0.1f * g;
                vv = 0.999f * ((const float*)&v4)[o] + 0.001f * g * g;
                vh = fmaxf(((const float*)&vh4)[o], vv);
            }
            ((float*)&mo)[o] = mm; ((float*)&vo)[o] = vv; ((float*)&vho)[o] = vh;
            float denom = sqrtf(vh) / sbc2 + 1e-8f;
            float fnew = fcc - 0.1f * (mm / bc1) / denom;
            ((float*)&fo)[o] = fnew;
            if (last) {
                float d = fnew - init[e + o];
                acc += (double)(d * d);
            }
        }
        if (!last) {
            *(float4*)(d_m + e) = mo;
            *(float4*)(d_v + e) = vo;
            *(float4*)(d_vh + e) = vho;
            *(float4*)(fn_ + e) = fo;
        }
    }

    if (last) {
        __shared__ double sd[256];
        sd[threadIdx.x] = acc; __syncthreads();
        for (int s = 128; s > 0; s >>= 1) {
            if (threadIdx.x < s) sd[threadIdx.x] += sd[threadIdx.x + s];
            __syncthreads();
        }
        if (threadIdx.x == 0) d_part[blockIdx.x] = sd[0];
    }
}

// ---------------------------------------------------------------------------
__global__ void k_red2(float* __restrict__ out)
{
    double acc = 0.0;
    for (int e = threadIdx.x; e < NBCHAIN; e += 1024) acc += d_part[e];
    __shared__ double sd[1024];
    sd[threadIdx.x] = acc; __syncthreads();
    for (int s = 512; s > 0; s >>= 1) {
        if (threadIdx.x < s) sd[threadIdx.x] += sd[threadIdx.x + s];
        __syncthreads();
    }
    if (threadIdx.x == 0) out[0] = (float)(sd[0] / (double)N3);
}

// ---------------------------------------------------------------------------
extern "C" void kernel_launch(void* const* d_in, const int* in_sizes, int n_in,
                              void* d_out, int out_size)
{
    (void)in_sizes; (void)n_in; (void)out_size;
    const float* x    = (const float*)d_in[0];
    const float* y    = (const float*)d_in[1];
    const float* init = (const float*)d_in[2];
    float* out = (float*)d_out;

    // W-axis pass params
    const int W_L = WW, W_S = DD, W_nlo4 = DD / 4, W_nch = WW / CHUNK;
    const int W_total = W_nlo4 * W_nch * HH;          // 76800 per field
    // H-axis pass params
    const int H_L = HH, H_S = WW * DD, H_nlo4 = (WW * DD) / 4, H_nch = HH / CHUNK;
    const int H_total = H_nlo4 * H_nch;               // 76800 per field
    const int BOX_BLOCKS = (W_total + 255) / 256;     // 300

    // precompute S_J, S_JJ: boxD -> boxW -> boxH into d_J (2 fields)
    k_boxd_pre<<<HH * WW, DD>>>(y);
    k_box1<<<dim3(BOX_BLOCKS, 2), 256>>>(0, 1, W_L, W_S, W_nlo4, W_nch, W_total);
    k_box1<<<dim3(BOX_BLOCKS, 2), 256>>>(1, 2, H_L, H_S, H_nlo4, H_nch, H_total);

    for (int t = 1; t <= 5; t++) {
        // flow src: t=1 -> init (0); odd t>=3 -> flowA (1); even -> flowB (2)
        int srcsel = (t == 1) ? 0 : ((t & 1) ? 1 : 2);
        int dstsel = (t & 1) ? 2 : 1;   // odd writes flowB, even writes flowA
        float bc1  = (float)(1.0 - pow(0.9, (double)t));
        float sbc2 = sqrtf((float)(1.0 - pow(0.999, (double)t)));

        // forward: warp + D-box (fused, stores Iw+jacobian), W-box, H-box+gf
        k_boxd_fwd<<<HH * WW, DD>>>(x, y, init, srcsel);
        k_box1<<<dim3(BOX_BLOCKS, 3), 256>>>(0, 1, W_L, W_S, W_nlo4, W_nch, W_total); // A->Bf
        k_boxh_gf<<<600, 256>>>();                                                    // Bf,J->A (g)
        // adjoint: H-box, W-box (D-box fused into chain)
        k_box1<<<dim3(BOX_BLOCKS, 3), 256>>>(0, 1, H_L, H_S, H_nlo4, H_nch, H_total); // A->Bf
        k_box1<<<dim3(BOX_BLOCKS, 3), 256>>>(1, 0, W_L, W_S, W_nlo4, W_nch, W_total); // Bf->A
        // chain rule + inline adjoint D-box + reg grad + Adam
        k_chain_adam<<<NBCHAIN, 256>>>(y, init, srcsel, dstsel,
                                       t == 1 ? 1 : 0, bc1, sbc2, t == 5 ? 1 : 0);
    }

    k_red2<<<1, 1024>>>(out);
}